// round 10
// baseline (speedup 1.0000x reference)
#include <cuda_runtime.h>

// Census loss, pair-symmetric, f32x2-packed, 4 adjacent pixels/thread,
// single-wave grid (512 blocks <= 148 SM x 4 blocks).
// t = 1 - 0.1*rc, rc = 1/(0.1+e^2), e = cx-cy, c = d*rsqrt(7.29+d^2),
// d = g3(b)-g3(a), g3 = r+g+b (the /3 folded into 0.81*9 = 7.29).
// Interior thread (96 pairs, all weights 2): res = 192 - 0.2*sum(rc).

#define IMG   256
#define IMG2  65536
#define SW    42     // padded pitch (floats): 4 left halo + 32 + 3 right + pad
#define SWR   38     // 32 + 6
#define NELEM (SWR * SW)   // 1596

typedef unsigned long long ull;

__device__ __forceinline__ float frsqrt_a(float x){ float r; asm("rsqrt.approx.f32 %0, %1;" : "=f"(r) : "f"(x)); return r; }
__device__ __forceinline__ float frcp_a  (float x){ float r; asm("rcp.approx.f32 %0, %1;"   : "=f"(r) : "f"(x)); return r; }

__device__ __forceinline__ ull pk(float lo, float hi){ ull r; asm("mov.b64 %0, {%1, %2};" : "=l"(r) : "f"(lo), "f"(hi)); return r; }
__device__ __forceinline__ float2 upk(ull v){ float2 f; asm("mov.b64 {%0, %1}, %2;" : "=f"(f.x), "=f"(f.y) : "l"(v)); return f; }
__device__ __forceinline__ ull fma2(ull a, ull b, ull c){ ull r; asm("fma.rn.f32x2 %0, %1, %2, %3;" : "=l"(r) : "l"(a), "l"(b), "l"(c)); return r; }
__device__ __forceinline__ ull mul2(ull a, ull b){ ull r; asm("mul.rn.f32x2 %0, %1, %2;" : "=l"(r) : "l"(a), "l"(b)); return r; }
__device__ __forceinline__ ull sub2(ull a, ull b){ ull r; asm("sub.rn.f32x2 %0, %1, %2;" : "=l"(r) : "l"(a), "l"(b)); return r; }

__device__ __forceinline__ ull lds64(const float* p){
    ull r; asm("ld.shared.b64 %0, [%1];" : "=l"(r) : "l"((size_t)__cvta_generic_to_shared(p))); return r;
}

// packed rc = 1/(0.1+e^2) for two pixel-pairs
__device__ __forceinline__ float2 pair_rc2(ull nbx, ull nby, ull cenx, ull ceny,
                                           ull C729, ull C01)
{
    ull dX = sub2(nbx, cenx);
    ull dY = sub2(nby, ceny);
    ull aX = fma2(dX, dX, C729);
    ull aY = fma2(dY, dY, C729);
    float2 a = upk(aX);
    ull rX = pk(frsqrt_a(a.x), frsqrt_a(a.y));
    float2 b = upk(aY);
    ull rY = pk(frsqrt_a(b.x), frsqrt_a(b.y));
    ull cx = mul2(dX, rX);
    ull cy = mul2(dY, rY);
    ull e  = sub2(cx, cy);
    ull dn = fma2(e, e, C01);
    float2 d = upk(dn);
    float2 rc;
    rc.x = frcp_a(d.x);
    rc.y = frcp_a(d.y);
    return rc;
}

template<bool BORDER>
__device__ __forceinline__ float census_body(const float* __restrict__ sx,
                                             const float* __restrict__ sy,
                                             int ty, int tx, int R, int C)
{
    const ull C729 = pk(7.29f, 7.29f);
    const ull C01  = pk(0.1f, 0.1f);

    // validity: vcw[k] = valid(C+k-3), k=0..9 ; vrow[d] = valid(R+d)
    float vrow[4], vcw[10];
    float va0 = 0.f, va1 = 0.f, va2 = 0.f, va3 = 0.f;
    if (BORDER) {
#pragma unroll
        for (int d = 0; d < 4; d++) vrow[d] = ((unsigned)(R + d - 3) < 250u) ? 1.f : 0.f;
#pragma unroll
        for (int k = 0; k < 10; k++) vcw[k] = ((unsigned)(C + k - 6) < 250u) ? 1.f : 0.f;
        va0 = vrow[0] * vcw[3];
        va1 = vrow[0] * vcw[4];
        va2 = vrow[0] * vcw[5];
        va3 = vrow[0] * vcw[6];
    }

    const int base0 = (ty + 3) * SW + 4 * tx;

    float accA = 0.f, accB = 0.f, accC = 0.f, accD = 0.f, accw = 0.f;
    ull cen0x, cen0y, cen1x, cen1y;

    // ---- center row (dy = 0): right-half offsets only ----
    {
        const float* px = sx + base0;
        const float* py = sy + base0;
        ull ux2 = lds64(px + 4), ux3 = lds64(px + 6), ux4 = lds64(px + 8), ux5 = lds64(px + 10);
        ull uy2 = lds64(py + 4), uy3 = lds64(py + 6), uy4 = lds64(py + 8), uy5 = lds64(py + 10);
        cen0x = ux2; cen0y = uy2;        // pixels C, C+1
        cen1x = ux3; cen1y = uy3;        // pixels C+2, C+3
        float2 x2 = upk(ux2), x3 = upk(ux3), x4 = upk(ux4), x5 = upk(ux5);
        float2 y2 = upk(uy2), y3 = upk(uy3), y4 = upk(uy4), y5 = upk(uy5);

        ull n4x = pk(x2.y, x3.x), n4y = pk(y2.y, y3.x);
        ull n6x = pk(x3.y, x4.x), n6y = pk(y3.y, y4.x);
        ull n8x = pk(x4.y, x5.x), n8y = pk(y4.y, y5.x);

        // pair-group 0: j = 4,5,6  (dx = 1,2,3)
        {
            float2 rc = pair_rc2(n4x, n4y, cen0x, cen0y, C729, C01);
            if (BORDER) { float w0 = fmaf(vrow[0], vcw[4], va0), w1 = fmaf(vrow[0], vcw[5], va1);
                          accw += w0 + w1; accA = fmaf(w0, rc.x, accA); accB = fmaf(w1, rc.y, accB); }
            else { accA += rc.x; accB += rc.y; }
        }
        {
            float2 rc = pair_rc2(ux3, uy3, cen0x, cen0y, C729, C01);
            if (BORDER) { float w0 = fmaf(vrow[0], vcw[5], va0), w1 = fmaf(vrow[0], vcw[6], va1);
                          accw += w0 + w1; accA = fmaf(w0, rc.x, accA); accB = fmaf(w1, rc.y, accB); }
            else { accA += rc.x; accB += rc.y; }
        }
        {
            float2 rc = pair_rc2(n6x, n6y, cen0x, cen0y, C729, C01);
            if (BORDER) { float w0 = fmaf(vrow[0], vcw[6], va0), w1 = fmaf(vrow[0], vcw[7], va1);
                          accw += w0 + w1; accA = fmaf(w0, rc.x, accA); accB = fmaf(w1, rc.y, accB); }
            else { accA += rc.x; accB += rc.y; }
        }
        // pair-group 1: j' = j+2 -> n6, u4, n8
        {
            float2 rc = pair_rc2(n6x, n6y, cen1x, cen1y, C729, C01);
            if (BORDER) { float w0 = fmaf(vrow[0], vcw[6], va2), w1 = fmaf(vrow[0], vcw[7], va3);
                          accw += w0 + w1; accC = fmaf(w0, rc.x, accC); accD = fmaf(w1, rc.y, accD); }
            else { accC += rc.x; accD += rc.y; }
        }
        {
            float2 rc = pair_rc2(ux4, uy4, cen1x, cen1y, C729, C01);
            if (BORDER) { float w0 = fmaf(vrow[0], vcw[7], va2), w1 = fmaf(vrow[0], vcw[8], va3);
                          accw += w0 + w1; accC = fmaf(w0, rc.x, accC); accD = fmaf(w1, rc.y, accD); }
            else { accC += rc.x; accD += rc.y; }
        }
        {
            float2 rc = pair_rc2(n8x, n8y, cen1x, cen1y, C729, C01);
            if (BORDER) { float w0 = fmaf(vrow[0], vcw[8], va2), w1 = fmaf(vrow[0], vcw[9], va3);
                          accw += w0 + w1; accC = fmaf(w0, rc.x, accC); accD = fmaf(w1, rc.y, accD); }
            else { accC += rc.x; accD += rc.y; }
        }
    }

    // ---- dy = 1..3: full dx = -3..3 for both pair-groups ----
#pragma unroll
    for (int dy = 1; dy < 4; dy++) {
        const float* px = sx + base0 + dy * SW;
        const float* py = sy + base0 + dy * SW;
        ull ux0 = lds64(px),     ux1 = lds64(px + 2), ux2 = lds64(px + 4),
            ux3 = lds64(px + 6), ux4 = lds64(px + 8), ux5 = lds64(px + 10);
        ull uy0 = lds64(py),     uy1 = lds64(py + 2), uy2 = lds64(py + 4),
            uy3 = lds64(py + 6), uy4 = lds64(py + 8), uy5 = lds64(py + 10);
        float2 x0 = upk(ux0), x1 = upk(ux1), x2 = upk(ux2), x3 = upk(ux3), x4 = upk(ux4), x5 = upk(ux5);
        float2 y0 = upk(uy0), y1 = upk(uy1), y2 = upk(uy2), y3 = upk(uy3), y4 = upk(uy4), y5 = upk(uy5);

#pragma unroll
        for (int j = 0; j < 7; j++) {
            // neighbor for pair-group 0 at position j
            ull n0xx, n0yy;
            switch (j) {
                case 0: n0xx = pk(x0.y, x1.x); n0yy = pk(y0.y, y1.x); break;
                case 1: n0xx = ux1;            n0yy = uy1;            break;
                case 2: n0xx = pk(x1.y, x2.x); n0yy = pk(y1.y, y2.x); break;
                case 3: n0xx = ux2;            n0yy = uy2;            break;
                case 4: n0xx = pk(x2.y, x3.x); n0yy = pk(y2.y, y3.x); break;
                case 5: n0xx = ux3;            n0yy = uy3;            break;
                default:n0xx = pk(x3.y, x4.x); n0yy = pk(y3.y, y4.x); break;
            }
            // neighbor for pair-group 1 at position j+2
            ull n1xx, n1yy;
            switch (j) {
                case 0: n1xx = pk(x1.y, x2.x); n1yy = pk(y1.y, y2.x); break;
                case 1: n1xx = ux2;            n1yy = uy2;            break;
                case 2: n1xx = pk(x2.y, x3.x); n1yy = pk(y2.y, y3.x); break;
                case 3: n1xx = ux3;            n1yy = uy3;            break;
                case 4: n1xx = pk(x3.y, x4.x); n1yy = pk(y3.y, y4.x); break;
                case 5: n1xx = ux4;            n1yy = uy4;            break;
                default:n1xx = pk(x4.y, x5.x); n1yy = pk(y4.y, y5.x); break;
            }
            float2 rc0 = pair_rc2(n0xx, n0yy, cen0x, cen0y, C729, C01);
            float2 rc1 = pair_rc2(n1xx, n1yy, cen1x, cen1y, C729, C01);
            if (BORDER) {
                float w0 = fmaf(vrow[dy], vcw[j],     va0);
                float w1 = fmaf(vrow[dy], vcw[j + 1], va1);
                float w2 = fmaf(vrow[dy], vcw[j + 2], va2);
                float w3 = fmaf(vrow[dy], vcw[j + 3], va3);
                accw += (w0 + w1) + (w2 + w3);
                accA = fmaf(w0, rc0.x, accA);
                accB = fmaf(w1, rc0.y, accB);
                accC = fmaf(w2, rc1.x, accC);
                accD = fmaf(w3, rc1.y, accD);
            } else {
                accA += rc0.x;
                accB += rc0.y;
                accC += rc1.x;
                accD += rc1.y;
            }
        }
    }

    float s = (accA + accB) + (accC + accD);
    // interior: 96 pairs, all weights 2: 2*(96 - 0.1*sum_rc)
    return BORDER ? fmaf(-0.1f, s, accw) : fmaf(-0.2f, s, 192.f);
}

__global__ __launch_bounds__(256, 4)
void census_loss_kernel(const float* __restrict__ x,
                        const float* __restrict__ y,
                        float* __restrict__ out)
{
    __shared__ __align__(16) float sgx[NELEM];
    __shared__ __align__(16) float sgy[NELEM];

    const int b    = blockIdx.z;
    const int row0 = blockIdx.y * 32;
    const int col0 = blockIdx.x * 32;
    const int tid  = threadIdx.y * 8 + threadIdx.x;

    const float* xb = x + (size_t)b * 3 * IMG2;
    const float* yb = y + (size_t)b * 3 * IMG2;

    // 3*grayscale tile + halo (left halo 4, top halo 3; zeros outside image)
#pragma unroll
    for (int it = 0; it < 7; it++) {
        int i = tid + it * 256;
        if (i < NELEM) {
            int lr = i / SW;
            int lc = i - lr * SW;
            int gr = row0 - 3 + lr;
            int gc = col0 - 4 + lc;
            float gx = 0.f, gy = 0.f;
            if ((unsigned)gr < 256u && (unsigned)gc < 256u) {
                int o = gr * IMG + gc;
                gx = xb[o] + xb[o + IMG2] + xb[o + 2 * IMG2];
                gy = yb[o] + yb[o + IMG2] + yb[o + 2 * IMG2];
            }
            sgx[i] = gx;
            sgy[i] = gy;
        }
    }
    __syncthreads();

    const int tx = threadIdx.x;          // 0..7  -> pixel cols 4tx .. 4tx+3
    const int ty = threadIdx.y;          // 0..31 -> pixel row
    const int R  = row0 + ty;
    const int C  = col0 + 4 * tx;

    const bool interior = (blockIdx.x - 1u < 6u) & (blockIdx.y - 1u < 6u);

    float acc = interior ? census_body<false>(sgx, sgy, ty, tx, R, C)
                         : census_body<true >(sgx, sgy, ty, tx, R, C);

    // warp + block reduction (8 warps)
#pragma unroll
    for (int s = 16; s > 0; s >>= 1)
        acc += __shfl_xor_sync(0xFFFFFFFFu, acc, s);

    __shared__ float wsum[8];
    if ((tid & 31) == 0) wsum[tid >> 5] = acc;
    __syncthreads();
    if (tid < 8) {
        float v = wsum[tid];
        v += __shfl_xor_sync(0xFFu, v, 4);
        v += __shfl_xor_sync(0xFFu, v, 2);
        v += __shfl_xor_sync(0xFFu, v, 1);
        if (tid == 0)
            atomicAdd(out, v * (1.f / 25690112.f));   // 1/(49*8*256*256)
    }
}

extern "C" void kernel_launch(void* const* d_in, const int* in_sizes, int n_in,
                              void* d_out, int out_size)
{
    const float* x = (const float*)d_in[0];
    const float* y = (const float*)d_in[1];
    float* out = (float*)d_out;

    cudaMemsetAsync(out, 0, sizeof(float));

    dim3 block(8, 32, 1);
    dim3 grid(8, 8, 8);   // 512 blocks -> one wave at 4 blocks/SM
    census_loss_kernel<<<grid, block>>>(x, y, out);
}

// round 11
// speedup vs baseline: 1.1317x; 1.1317x over previous
#include <cuda_runtime.h>

// Census loss, pair-symmetric, f32x2-packed, 2 adjacent pixels/thread.
// 2-MUFU formulation: e^2 = cx^2+cy^2-2cxcy computed from ONE rsqrt(PX*PY):
//   u = rsqrt(PX*PY); cx*cy = dX*dY*u; cx^2 = dX^2*PY*u^2; cy^2 = dY^2*PX*u^2
//   rc = rcp(0.1+e^2);  t = 1-0.1*rc
// d = g3(b)-g3(a), g3 = r+g+b (the /3 folded into 0.81*9 = 7.29).
// Interior thread (48 pairs, all weights 2): res = 96 - 0.2*sum(rc).
// Pitch-40 smem rows, LEFT halo 4 -> aligned LDS.64 for centers/even-dx pairs.

#define IMG   256
#define IMG2  65536
#define TCOLS 32
#define TROWS 16
#define SW    40   // padded pitch (floats): 4 left halo + 32 + 3 right + 1 pad
#define SWR   22   // TROWS + 6

typedef unsigned long long ull;

__device__ __forceinline__ float frsqrt_a(float x){ float r; asm("rsqrt.approx.f32 %0, %1;" : "=f"(r) : "f"(x)); return r; }
__device__ __forceinline__ float frcp_a  (float x){ float r; asm("rcp.approx.f32 %0, %1;"   : "=f"(r) : "f"(x)); return r; }

__device__ __forceinline__ ull pk(float lo, float hi){ ull r; asm("mov.b64 %0, {%1, %2};" : "=l"(r) : "f"(lo), "f"(hi)); return r; }
__device__ __forceinline__ float2 upk(ull v){ float2 f; asm("mov.b64 {%0, %1}, %2;" : "=f"(f.x), "=f"(f.y) : "l"(v)); return f; }
__device__ __forceinline__ ull fma2(ull a, ull b, ull c){ ull r; asm("fma.rn.f32x2 %0, %1, %2, %3;" : "=l"(r) : "l"(a), "l"(b), "l"(c)); return r; }
__device__ __forceinline__ ull mul2(ull a, ull b){ ull r; asm("mul.rn.f32x2 %0, %1, %2;" : "=l"(r) : "l"(a), "l"(b)); return r; }
__device__ __forceinline__ ull add2(ull a, ull b){ ull r; asm("add.rn.f32x2 %0, %1, %2;" : "=l"(r) : "l"(a), "l"(b)); return r; }
__device__ __forceinline__ ull sub2(ull a, ull b){ ull r; asm("sub.rn.f32x2 %0, %1, %2;" : "=l"(r) : "l"(a), "l"(b)); return r; }

__device__ __forceinline__ ull lds64(const float* p){
    ull r; asm("ld.shared.b64 %0, [%1];" : "=l"(r) : "l"((size_t)__cvta_generic_to_shared(p))); return r;
}

// packed rc = 1/(0.1+e^2) for two pixel-pairs -- 2 MUFU per pair
__device__ __forceinline__ float2 pair_rc2(ull nbx, ull nby, ull cenx, ull ceny,
                                           ull C729, ull C01, ull CN2)
{
    ull dX  = sub2(nbx, cenx);
    ull dY  = sub2(nby, ceny);
    ull dx2 = mul2(dX, dX);
    ull dy2 = mul2(dY, dY);
    ull PX  = add2(dx2, C729);
    ull PY  = add2(dy2, C729);
    ull PP  = mul2(PX, PY);
    float2 pp = upk(PP);
    ull u   = pk(frsqrt_a(pp.x), frsqrt_a(pp.y));   // 1/sqrt(PX*PY)
    ull u2  = mul2(u, u);
    ull w   = mul2(dX, dY);
    ull s   = fma2(dx2, PY, mul2(dy2, PX));         // dX^2*PY + dY^2*PX
    ull t1  = mul2(w, u);                           // cx*cy
    ull e2  = fma2(u2, s, mul2(t1, CN2));           // cx^2+cy^2-2cxcy
    ull dn  = add2(e2, C01);
    float2 d = upk(dn);
    float2 rc;
    rc.x = frcp_a(d.x);
    rc.y = frcp_a(d.y);
    return rc;
}

template<bool BORDER>
__device__ __forceinline__ float census_body(const float* __restrict__ sx,
                                             const float* __restrict__ sy,
                                             int ty, int tx, int r, int c0)
{
    const ull C729 = pk(7.29f, 7.29f);
    const ull C01  = pk(0.1f, 0.1f);
    const ull CN2  = pk(-2.f, -2.f);

    float vrow[4], vcw[8];
    float va0 = 0.f, va1 = 0.f;
    if (BORDER) {
#pragma unroll
        for (int d = 0; d < 4; d++) vrow[d] = ((unsigned)(r + d - 3) < 250u) ? 1.f : 0.f;
#pragma unroll
        for (int j = 0; j < 8; j++) vcw[j] = ((unsigned)(c0 - 6 + j) < 250u) ? 1.f : 0.f;
        va0 = vrow[0] * vcw[3];
        va1 = vrow[0] * vcw[4];
    }

    const int rowoff0 = (ty + 3) * SW + 2 * tx;

    float accA = 0.f, accB = 0.f, accw = 0.f;

    // ---- center row (dy = 0): aligned center pair ----
    ull cenx, ceny;
    {
        const float* px = sx + rowoff0;
        const float* py = sy + rowoff0;
        ull ux2 = lds64(px + 4), ux3 = lds64(px + 6), ux4 = lds64(px + 8);
        ull uy2 = lds64(py + 4), uy3 = lds64(py + 6), uy4 = lds64(py + 8);
        cenx = ux2; ceny = uy2;
        float2 x2 = upk(ux2), x3 = upk(ux3), x4 = upk(ux4);
        float2 y2 = upk(uy2), y3 = upk(uy3), y4 = upk(uy4);

        {   // dx=1
            float2 rc = pair_rc2(pk(x2.y, x3.x), pk(y2.y, y3.x), cenx, ceny, C729, C01, CN2);
            if (BORDER) { float w0 = fmaf(vrow[0], vcw[4], va0), w1 = fmaf(vrow[0], vcw[5], va1);
                          accw += w0 + w1; accA = fmaf(w0, rc.x, accA); accB = fmaf(w1, rc.y, accB); }
            else { accA += rc.x; accB += rc.y; }
        }
        {   // dx=2 (aligned)
            float2 rc = pair_rc2(ux3, uy3, cenx, ceny, C729, C01, CN2);
            if (BORDER) { float w0 = fmaf(vrow[0], vcw[5], va0), w1 = fmaf(vrow[0], vcw[6], va1);
                          accw += w0 + w1; accA = fmaf(w0, rc.x, accA); accB = fmaf(w1, rc.y, accB); }
            else { accA += rc.x; accB += rc.y; }
        }
        {   // dx=3
            float2 rc = pair_rc2(pk(x3.y, x4.x), pk(y3.y, y4.x), cenx, ceny, C729, C01, CN2);
            if (BORDER) { float w0 = fmaf(vrow[0], vcw[6], va0), w1 = fmaf(vrow[0], vcw[7], va1);
                          accw += w0 + w1; accA = fmaf(w0, rc.x, accA); accB = fmaf(w1, rc.y, accB); }
            else { accA += rc.x; accB += rc.y; }
        }
    }

    // ---- dy = 1..3: dx = -3..3, neighbors consumed immediately ----
#pragma unroll
    for (int dy = 1; dy < 4; dy++) {
        const float* px = sx + rowoff0 + dy * SW;
        const float* py = sy + rowoff0 + dy * SW;
        ull ux0 = lds64(px), ux1 = lds64(px + 2), ux2 = lds64(px + 4), ux3 = lds64(px + 6), ux4 = lds64(px + 8);
        ull uy0 = lds64(py), uy1 = lds64(py + 2), uy2 = lds64(py + 4), uy3 = lds64(py + 6), uy4 = lds64(py + 8);
        float2 x0 = upk(ux0), x1 = upk(ux1), x2 = upk(ux2), x3 = upk(ux3), x4 = upk(ux4);
        float2 y0 = upk(uy0), y1 = upk(uy1), y2 = upk(uy2), y3 = upk(uy3), y4 = upk(uy4);

#pragma unroll
        for (int j = 0; j < 7; j++) {
            ull nbx, nby;
            switch (j) {
                case 0: nbx = pk(x0.y, x1.x); nby = pk(y0.y, y1.x); break;  // dx=-3
                case 1: nbx = ux1;            nby = uy1;            break;  // dx=-2
                case 2: nbx = pk(x1.y, x2.x); nby = pk(y1.y, y2.x); break;  // dx=-1
                case 3: nbx = ux2;            nby = uy2;            break;  // dx= 0
                case 4: nbx = pk(x2.y, x3.x); nby = pk(y2.y, y3.x); break;  // dx=+1
                case 5: nbx = ux3;            nby = uy3;            break;  // dx=+2
                default:nbx = pk(x3.y, x4.x); nby = pk(y3.y, y4.x); break;  // dx=+3
            }
            float2 rc = pair_rc2(nbx, nby, cenx, ceny, C729, C01, CN2);
            if (BORDER) {
                float w0 = fmaf(vrow[dy], vcw[j], va0);
                float w1 = fmaf(vrow[dy], vcw[j + 1], va1);
                accw += w0 + w1;
                accA = fmaf(w0, rc.x, accA);
                accB = fmaf(w1, rc.y, accB);
            } else {
                accA += rc.x;
                accB += rc.y;
            }
        }
    }

    float s = accA + accB;
    return BORDER ? fmaf(-0.1f, s, accw) : fmaf(-0.2f, s, 96.f);
}

__global__ __launch_bounds__(256, 4)
void census_loss_kernel(const float* __restrict__ x,
                        const float* __restrict__ y,
                        float* __restrict__ out)
{
    __shared__ __align__(16) float sgx[SWR * SW];
    __shared__ __align__(16) float sgy[SWR * SW];

    const int b    = blockIdx.z;
    const int row0 = blockIdx.y * TROWS;
    const int col0 = blockIdx.x * TCOLS;
    const int tid  = threadIdx.y * 16 + threadIdx.x;

    const float* xb = x + (size_t)b * 3 * IMG2;
    const float* yb = y + (size_t)b * 3 * IMG2;

    // 3*grayscale tile + halo (left halo 4; zeros outside image)
    for (int i = tid; i < SWR * SW; i += 256) {
        int lr = i / SW;
        int lc = i - lr * SW;
        int gr = row0 - 3 + lr;
        int gc = col0 - 4 + lc;
        float gx = 0.f, gy = 0.f;
        if ((unsigned)gr < 256u && (unsigned)gc < 256u) {
            int o = gr * IMG + gc;
            gx = xb[o] + xb[o + IMG2] + xb[o + 2 * IMG2];
            gy = yb[o] + yb[o + IMG2] + yb[o + 2 * IMG2];
        }
        sgx[i] = gx;
        sgy[i] = gy;
    }
    __syncthreads();

    const int tx = threadIdx.x;          // 0..15 -> pixel cols 2tx, 2tx+1
    const int ty = threadIdx.y;          // 0..15 -> pixel row
    const int r  = row0 + ty;
    const int c0 = col0 + 2 * tx;

    const bool interior = (blockIdx.x - 1u < 6u) & (blockIdx.y - 1u < 14u);

    float acc = interior ? census_body<false>(sgx, sgy, ty, tx, r, c0)
                         : census_body<true >(sgx, sgy, ty, tx, r, c0);

    // warp + block reduction
#pragma unroll
    for (int s = 16; s > 0; s >>= 1)
        acc += __shfl_xor_sync(0xFFFFFFFFu, acc, s);

    __shared__ float wsum[8];
    if ((tid & 31) == 0) wsum[tid >> 5] = acc;
    __syncthreads();
    if (tid < 8) {
        float v = wsum[tid];
        v += __shfl_xor_sync(0xFFu, v, 4);
        v += __shfl_xor_sync(0xFFu, v, 2);
        v += __shfl_xor_sync(0xFFu, v, 1);
        if (tid == 0)
            atomicAdd(out, v * (1.f / 25690112.f));   // 1/(49*8*256*256)
    }
}

extern "C" void kernel_launch(void* const* d_in, const int* in_sizes, int n_in,
                              void* d_out, int out_size)
{
    const float* x = (const float*)d_in[0];
    const float* y = (const float*)d_in[1];
    float* out = (float*)d_out;

    cudaMemsetAsync(out, 0, sizeof(float));

    dim3 block(16, 16, 1);
    dim3 grid(IMG / TCOLS, IMG / TROWS, 8);   // 8 x 16 x 8 = 1024 blocks
    census_loss_kernel<<<grid, block>>>(x, y, out);
}